// round 1
// baseline (speedup 1.0000x reference)
#include <cuda_runtime.h>
#include <cuda_bf16.h>
#include <math.h>

// Problem constants
#define B_  2
#define N_  2048
#define C_  1024
#define H_  16
#define HD_ 64

// Scratch (no allocation allowed -> device globals)
__device__ float g_qkv[B_ * N_ * 3 * C_];          // [B,N,3,H,hd]
__device__ float g_q[B_ * H_ * N_ * HD_];          // [B,H,N,hd]
__device__ float g_k[B_ * H_ * N_ * HD_];
__device__ float g_v[B_ * H_ * N_ * HD_];
__device__ float g_att[B_ * N_ * C_];              // [B,N,C]

// ---------------------------------------------------------------------------
// SGEMM-NT: C[m][n] = sum_k A[m][k] * W[n][k]  (+ bias[n] if bias != null)
// A: [M,K] row-major, W: [N,K] row-major. M,N multiples of 128, K mult of 16.
// ---------------------------------------------------------------------------
__global__ __launch_bounds__(256) void sgemm_nt(
    const float* __restrict__ A, const float* __restrict__ W,
    const float* __restrict__ bias, float* __restrict__ C,
    int M, int N, int K)
{
    __shared__ alignas(16) float As[16][132];
    __shared__ alignas(16) float Bs[16][132];

    const int t  = threadIdx.x;
    const int tx = t & 15;
    const int ty = t >> 4;
    const int bm = blockIdx.y * 128;
    const int bn = blockIdx.x * 128;

    float o[8][8];
#pragma unroll
    for (int i = 0; i < 8; i++)
#pragma unroll
        for (int j = 0; j < 8; j++) o[i][j] = 0.f;

    for (int kt = 0; kt < K; kt += 16) {
#pragma unroll
        for (int i = 0; i < 2; i++) {
            int v   = t + i * 256;          // 0..511 float4 slots
            int row = v >> 2;
            int kc4 = (v & 3) * 4;
            float4 a4 = *(const float4*)&A[(size_t)(bm + row) * K + kt + kc4];
            As[kc4 + 0][row] = a4.x; As[kc4 + 1][row] = a4.y;
            As[kc4 + 2][row] = a4.z; As[kc4 + 3][row] = a4.w;
            float4 b4 = *(const float4*)&W[(size_t)(bn + row) * K + kt + kc4];
            Bs[kc4 + 0][row] = b4.x; Bs[kc4 + 1][row] = b4.y;
            Bs[kc4 + 2][row] = b4.z; Bs[kc4 + 3][row] = b4.w;
        }
        __syncthreads();

#pragma unroll
        for (int k = 0; k < 16; k++) {
            float4 a0 = *(const float4*)&As[k][ty * 4];
            float4 a1 = *(const float4*)&As[k][ty * 4 + 64];
            float4 b0 = *(const float4*)&Bs[k][tx * 4];
            float4 b1 = *(const float4*)&Bs[k][tx * 4 + 64];
            float a[8] = {a0.x, a0.y, a0.z, a0.w, a1.x, a1.y, a1.z, a1.w};
            float b[8] = {b0.x, b0.y, b0.z, b0.w, b1.x, b1.y, b1.z, b1.w};
#pragma unroll
            for (int i = 0; i < 8; i++)
#pragma unroll
                for (int j = 0; j < 8; j++) o[i][j] += a[i] * b[j];
        }
        __syncthreads();
    }

#pragma unroll
    for (int i = 0; i < 8; i++) {
        int m = bm + ty * 4 + (i & 3) + (i >> 2) * 64;
#pragma unroll
        for (int j = 0; j < 8; j++) {
            int n = bn + tx * 4 + (j & 3) + (j >> 2) * 64;
            float val = o[i][j];
            if (bias) val += bias[n];
            C[(size_t)m * N + n] = val;
        }
    }
}

// ---------------------------------------------------------------------------
// RMSNorm + Rotary + layout transform.  One warp per (b,n,h).
// qkv: [B,N,3,H,hd]  ->  Q/K/V: [B,H,N,hd]
// ---------------------------------------------------------------------------
__global__ __launch_bounds__(256) void norm_rope(
    const float* __restrict__ qkv,
    const float* __restrict__ qw, const float* __restrict__ kw,
    const float* __restrict__ cosb, const float* __restrict__ sinb,
    float* __restrict__ Q, float* __restrict__ K, float* __restrict__ V)
{
    int warp = (blockIdx.x * blockDim.x + threadIdx.x) >> 5;
    int lane = threadIdx.x & 31;
    if (warp >= B_ * N_ * H_) return;
    int h = warp % H_;
    int n = (warp / H_) % N_;
    int b = warp / (H_ * N_);

    const float* base = qkv + (size_t)(b * N_ + n) * 3 * C_ + h * HD_;
    int d0 = lane * 2;
    float q0 = base[d0],          q1 = base[d0 + 1];
    float k0 = base[C_ + d0],     k1 = base[C_ + d0 + 1];
    float v0 = base[2 * C_ + d0], v1 = base[2 * C_ + d0 + 1];

    float qs = q0 * q0 + q1 * q1;
    float ks = k0 * k0 + k1 * k1;
#pragma unroll
    for (int off = 16; off; off >>= 1) {
        qs += __shfl_xor_sync(0xffffffffu, qs, off);
        ks += __shfl_xor_sync(0xffffffffu, ks, off);
    }
    float qr = rsqrtf(qs * (1.f / HD_) + 1e-6f);
    float kr = rsqrtf(ks * (1.f / HD_) + 1e-6f);
    q0 = qw[d0] * q0 * qr; q1 = qw[d0 + 1] * q1 * qr;
    k0 = kw[d0] * k0 * kr; k1 = kw[d0 + 1] * k1 * kr;

    float c = cosb[n * 32 + lane];
    float s = sinb[n * 32 + lane];
    float qo0 = q0 * c - q1 * s, qo1 = q0 * s + q1 * c;
    float ko0 = k0 * c - k1 * s, ko1 = k0 * s + k1 * c;

    size_t oi = (((size_t)(b * H_ + h)) * N_ + n) * HD_ + d0;
    Q[oi] = qo0; Q[oi + 1] = qo1;
    K[oi] = ko0; K[oi + 1] = ko1;
    V[oi] = v0;  V[oi + 1] = v1;
}

// ---------------------------------------------------------------------------
// Causal flash attention. Block = 64 q-rows of one (b,h); 32-key tiles.
// Q/K/V: [B,H,N,hd].  Output written in [B,N,H*hd] layout.
// ---------------------------------------------------------------------------
__global__ __launch_bounds__(256) void attn_kernel(
    const float* __restrict__ Q, const float* __restrict__ K,
    const float* __restrict__ V, float* __restrict__ O)
{
    const int qt = blockIdx.x;   // q tile (64 rows)
    const int h  = blockIdx.y;
    const int b  = blockIdx.z;

    __shared__ alignas(16) float sQt[64][68];   // [d][r]
    __shared__ float sKt[64][33];               // [d][j]
    __shared__ alignas(16) float sV[32][68];    // [j][d]
    __shared__ float sS[64][33];                // [r][j]
    __shared__ float sM[64], sL[64], sAl[64];

    const int t    = threadIdx.x;
    const int tx   = t & 15;
    const int ty   = t >> 4;
    const int warp = t >> 5;
    const int lane = t & 31;

    size_t qbase = (((size_t)(b * H_ + h)) * N_ + qt * 64) * HD_;
#pragma unroll
    for (int i = 0; i < 16; i++) {
        int idx = t + i * 256;
        int r = idx >> 6, d = idx & 63;
        sQt[d][r] = Q[qbase + idx];
    }
    if (t < 64) { sM[t] = -INFINITY; sL[t] = 0.f; }

    float o[4][4];
#pragma unroll
    for (int i = 0; i < 4; i++)
#pragma unroll
        for (int j = 0; j < 4; j++) o[i][j] = 0.f;

    const int nkt = 2 * qt + 2;
    for (int kb = 0; kb < nkt; kb++) {
        __syncthreads();
        size_t kbase = (((size_t)(b * H_ + h)) * N_ + kb * 32) * HD_;
#pragma unroll
        for (int i = 0; i < 8; i++) {
            int idx = t + i * 256;
            int j = idx >> 6, d = idx & 63;
            sKt[d][j] = K[kbase + idx];
            sV[j][d]  = V[kbase + idx];
        }
        __syncthreads();

        // S = Q @ K^T on this tile
        float s[4][2] = {{0.f, 0.f}, {0.f, 0.f}, {0.f, 0.f}, {0.f, 0.f}};
#pragma unroll
        for (int d = 0; d < 64; d++) {
            float4 a = *(const float4*)&sQt[d][ty * 4];
            float b0 = sKt[d][tx * 2];
            float b1 = sKt[d][tx * 2 + 1];
            s[0][0] += a.x * b0; s[0][1] += a.x * b1;
            s[1][0] += a.y * b0; s[1][1] += a.y * b1;
            s[2][0] += a.z * b0; s[2][1] += a.z * b1;
            s[3][0] += a.w * b0; s[3][1] += a.w * b1;
        }
        const float scale = 0.125f;   // hd^-0.5
        const bool diag = (kb >= 2 * qt);
#pragma unroll
        for (int rr = 0; rr < 4; rr++)
#pragma unroll
            for (int cc = 0; cc < 2; cc++) {
                float val = s[rr][cc] * scale;
                if (diag && (kb * 32 + tx * 2 + cc) > (qt * 64 + ty * 4 + rr))
                    val = -1e30f;
                sS[ty * 4 + rr][tx * 2 + cc] = val;
            }
        __syncthreads();

        // online softmax: warp w -> rows 8w..8w+7, lane = key column
#pragma unroll
        for (int rr = 0; rr < 8; rr++) {
            int r = warp * 8 + rr;
            float v = sS[r][lane];
            float m = v;
#pragma unroll
            for (int off = 16; off; off >>= 1)
                m = fmaxf(m, __shfl_xor_sync(0xffffffffu, m, off));
            float mo = sM[r];
            float mn = fmaxf(mo, m);
            float p = __expf(v - mn);
            float sum = p;
#pragma unroll
            for (int off = 16; off; off >>= 1)
                sum += __shfl_xor_sync(0xffffffffu, sum, off);
            sS[r][lane] = p;
            if (lane == 0) {
                float al = __expf(mo - mn);
                sAl[r] = al;
                sM[r]  = mn;
                sL[r]  = sL[r] * al + sum;
            }
        }
        __syncthreads();

        // O = O*alpha + P @ V
#pragma unroll
        for (int rr = 0; rr < 4; rr++) {
            float al = sAl[ty * 4 + rr];
            o[rr][0] *= al; o[rr][1] *= al; o[rr][2] *= al; o[rr][3] *= al;
        }
#pragma unroll
        for (int j = 0; j < 32; j++) {
            float4 v4 = *(const float4*)&sV[j][tx * 4];
#pragma unroll
            for (int rr = 0; rr < 4; rr++) {
                float p = sS[ty * 4 + rr][j];
                o[rr][0] += p * v4.x; o[rr][1] += p * v4.y;
                o[rr][2] += p * v4.z; o[rr][3] += p * v4.w;
            }
        }
    }
    __syncthreads();

#pragma unroll
    for (int rr = 0; rr < 4; rr++) {
        int r = ty * 4 + rr;
        float inv = 1.f / sL[r];
        int qg = qt * 64 + r;
        size_t oi = ((size_t)(b * N_) + qg) * C_ + h * HD_ + tx * 4;
        O[oi + 0] = o[rr][0] * inv;
        O[oi + 1] = o[rr][1] * inv;
        O[oi + 2] = o[rr][2] * inv;
        O[oi + 3] = o[rr][3] * inv;
    }
}

// ---------------------------------------------------------------------------
extern "C" void kernel_launch(void* const* d_in, const int* in_sizes, int n_in,
                              void* d_out, int out_size)
{
    const float* x      = (const float*)d_in[0];
    const float* qkv_w  = (const float*)d_in[1];
    const float* qnw    = (const float*)d_in[2];
    const float* knw    = (const float*)d_in[3];
    const float* proj_w = (const float*)d_in[4];
    const float* proj_b = (const float*)d_in[5];
    const float* pcos   = (const float*)d_in[6];
    const float* psin   = (const float*)d_in[7];
    // d_in[8] = mask (tril) — causal, handled analytically
    float* out = (float*)d_out;

    void *p_qkv, *p_q, *p_k, *p_v, *p_att;
    cudaGetSymbolAddress(&p_qkv, g_qkv);
    cudaGetSymbolAddress(&p_q,   g_q);
    cudaGetSymbolAddress(&p_k,   g_k);
    cudaGetSymbolAddress(&p_v,   g_v);
    cudaGetSymbolAddress(&p_att, g_att);
    float* qkv = (float*)p_qkv;
    float* Qb  = (float*)p_q;
    float* Kb  = (float*)p_k;
    float* Vb  = (float*)p_v;
    float* att = (float*)p_att;

    const int M = B_ * N_;   // 4096

    // 1) QKV projection: [4096,1024] @ [3072,1024]^T -> [4096,3072]
    sgemm_nt<<<dim3(3 * C_ / 128, M / 128), 256>>>(x, qkv_w, nullptr, qkv,
                                                   M, 3 * C_, C_);
    // 2) RMSNorm + RoPE + transpose
    norm_rope<<<(B_ * N_ * H_ * 32) / 256, 256>>>(qkv, qnw, knw, pcos, psin,
                                                  Qb, Kb, Vb);
    // 3) Causal flash attention
    attn_kernel<<<dim3(N_ / 64, H_, B_), 256>>>(Qb, Kb, Vb, att);
    // 4) Output projection + bias
    sgemm_nt<<<dim3(C_ / 128, M / 128), 256>>>(att, proj_w, proj_b, out,
                                               M, C_, C_);
}

// round 2
// speedup vs baseline: 1.4110x; 1.4110x over previous
#include <cuda_runtime.h>
#include <cuda_bf16.h>
#include <math.h>

// Problem constants
#define B_  2
#define N_  2048
#define C_  1024
#define H_  16
#define HD_ 64

// Scratch (no allocation allowed -> device globals)
__device__ float g_qkv[B_ * N_ * 3 * C_];          // [B,N,3,H,hd]
__device__ float g_q[B_ * H_ * N_ * HD_];          // [B,H,N,hd]
__device__ float g_k[B_ * H_ * N_ * HD_];
__device__ float g_v[B_ * H_ * N_ * HD_];
__device__ float g_att[B_ * N_ * C_];              // [B,N,C]

// ---------------------------------------------------------------------------
// TF32 helpers
// ---------------------------------------------------------------------------
__device__ __forceinline__ float f2tf32(float x) {
    unsigned r;
    asm("cvt.rna.tf32.f32 %0, %1;" : "=r"(r) : "f"(x));
    return __uint_as_float(r);
}

__device__ __forceinline__ void mma1688(
    float& c0, float& c1, float& c2, float& c3,
    unsigned a0, unsigned a1, unsigned a2, unsigned a3,
    unsigned b0, unsigned b1)
{
    asm volatile(
        "mma.sync.aligned.m16n8k8.row.col.f32.tf32.tf32.f32 "
        "{%0,%1,%2,%3},{%4,%5,%6,%7},{%8,%9},{%0,%1,%2,%3};"
        : "+f"(c0), "+f"(c1), "+f"(c2), "+f"(c3)
        : "r"(a0), "r"(a1), "r"(a2), "r"(a3), "r"(b0), "r"(b1));
}

// ---------------------------------------------------------------------------
// TF32 tensor-core GEMM-NT: C[m][n] = sum_k A[m][k]*W[n][k] (+bias[n])
// A:[M,K] row-major, W:[N,K] row-major. M,N mult of 128, K mult of 16.
// Block 256 thr = 8 warps (2m x 4n), warp tile 64x32, k-step 16.
// ---------------------------------------------------------------------------
#define GPAD 20
__global__ __launch_bounds__(256) void gemm_tf32(
    const float* __restrict__ A, const float* __restrict__ W,
    const float* __restrict__ bias, float* __restrict__ Cout,
    int M, int N, int K)
{
    __shared__ alignas(16) float As[2][128 * GPAD];
    __shared__ alignas(16) float Bs[2][128 * GPAD];

    const int t    = threadIdx.x;
    const int bm   = blockIdx.y * 128;
    const int bn   = blockIdx.x * 128;
    const int warp = t >> 5;
    const int lane = t & 31;
    const int wm   = (warp >> 2) * 64;   // 0 or 64
    const int wn   = (warp & 3) * 32;    // 0..96
    const int g    = lane >> 2;          // group id 0..7
    const int tg   = lane & 3;           // thread in group

    float c[4][4][4];
#pragma unroll
    for (int i = 0; i < 4; i++)
#pragma unroll
        for (int j = 0; j < 4; j++)
#pragma unroll
            for (int q = 0; q < 4; q++) c[i][j][q] = 0.f;

    const int lr  = t >> 2;          // load row 0..63 (and +64)
    const int lkc = (t & 3) * 4;     // load col 0,4,8,12

    float4 pa0, pa1, pb0, pb1;

    // prologue: tile 0
    pa0 = *(const float4*)&A[(size_t)(bm + lr)      * K + lkc];
    pa1 = *(const float4*)&A[(size_t)(bm + lr + 64) * K + lkc];
    pb0 = *(const float4*)&W[(size_t)(bn + lr)      * K + lkc];
    pb1 = *(const float4*)&W[(size_t)(bn + lr + 64) * K + lkc];
    {
        float4 ca0 = {f2tf32(pa0.x), f2tf32(pa0.y), f2tf32(pa0.z), f2tf32(pa0.w)};
        float4 ca1 = {f2tf32(pa1.x), f2tf32(pa1.y), f2tf32(pa1.z), f2tf32(pa1.w)};
        float4 cb0 = {f2tf32(pb0.x), f2tf32(pb0.y), f2tf32(pb0.z), f2tf32(pb0.w)};
        float4 cb1 = {f2tf32(pb1.x), f2tf32(pb1.y), f2tf32(pb1.z), f2tf32(pb1.w)};
        *(float4*)&As[0][lr * GPAD + lkc]        = ca0;
        *(float4*)&As[0][(lr + 64) * GPAD + lkc] = ca1;
        *(float4*)&Bs[0][lr * GPAD + lkc]        = cb0;
        *(float4*)&Bs[0][(lr + 64) * GPAD + lkc] = cb1;
    }
    __syncthreads();

    int buf = 0;
    for (int kt = 0; kt < K; kt += 16) {
        const bool more = (kt + 16) < K;
        if (more) {
            pa0 = *(const float4*)&A[(size_t)(bm + lr)      * K + kt + 16 + lkc];
            pa1 = *(const float4*)&A[(size_t)(bm + lr + 64) * K + kt + 16 + lkc];
            pb0 = *(const float4*)&W[(size_t)(bn + lr)      * K + kt + 16 + lkc];
            pb1 = *(const float4*)&W[(size_t)(bn + lr + 64) * K + kt + 16 + lkc];
        }

        const float* __restrict__ as = As[buf];
        const float* __restrict__ bs = Bs[buf];
#pragma unroll
        for (int ka = 0; ka < 2; ka++) {
            const int kb = ka * 8;
            unsigned af[4][4], bf[4][2];
#pragma unroll
            for (int am = 0; am < 4; am++) {
                const int m0 = wm + am * 16;
                af[am][0] = __float_as_uint(as[(m0 + g)     * GPAD + kb + tg]);
                af[am][1] = __float_as_uint(as[(m0 + 8 + g) * GPAD + kb + tg]);
                af[am][2] = __float_as_uint(as[(m0 + g)     * GPAD + kb + tg + 4]);
                af[am][3] = __float_as_uint(as[(m0 + 8 + g) * GPAD + kb + tg + 4]);
            }
#pragma unroll
            for (int an = 0; an < 4; an++) {
                const int n0 = wn + an * 8;
                bf[an][0] = __float_as_uint(bs[(n0 + g) * GPAD + kb + tg]);
                bf[an][1] = __float_as_uint(bs[(n0 + g) * GPAD + kb + tg + 4]);
            }
#pragma unroll
            for (int am = 0; am < 4; am++)
#pragma unroll
                for (int an = 0; an < 4; an++)
                    mma1688(c[am][an][0], c[am][an][1], c[am][an][2], c[am][an][3],
                            af[am][0], af[am][1], af[am][2], af[am][3],
                            bf[an][0], bf[an][1]);
        }

        if (more) {
            const int nb = buf ^ 1;
            float4 ca0 = {f2tf32(pa0.x), f2tf32(pa0.y), f2tf32(pa0.z), f2tf32(pa0.w)};
            float4 ca1 = {f2tf32(pa1.x), f2tf32(pa1.y), f2tf32(pa1.z), f2tf32(pa1.w)};
            float4 cb0 = {f2tf32(pb0.x), f2tf32(pb0.y), f2tf32(pb0.z), f2tf32(pb0.w)};
            float4 cb1 = {f2tf32(pb1.x), f2tf32(pb1.y), f2tf32(pb1.z), f2tf32(pb1.w)};
            *(float4*)&As[nb][lr * GPAD + lkc]        = ca0;
            *(float4*)&As[nb][(lr + 64) * GPAD + lkc] = ca1;
            *(float4*)&Bs[nb][lr * GPAD + lkc]        = cb0;
            *(float4*)&Bs[nb][(lr + 64) * GPAD + lkc] = cb1;
            __syncthreads();
            buf = nb;
        }
    }

    // epilogue
#pragma unroll
    for (int am = 0; am < 4; am++) {
        const int r0 = bm + wm + am * 16 + g;
#pragma unroll
        for (int an = 0; an < 4; an++) {
            const int cc = bn + wn + an * 8 + 2 * tg;
            float b0 = 0.f, b1 = 0.f;
            if (bias) { b0 = bias[cc]; b1 = bias[cc + 1]; }
            float2 v0 = {c[am][an][0] + b0, c[am][an][1] + b1};
            float2 v1 = {c[am][an][2] + b0, c[am][an][3] + b1};
            *(float2*)&Cout[(size_t)r0 * N + cc]       = v0;
            *(float2*)&Cout[(size_t)(r0 + 8) * N + cc] = v1;
        }
    }
}

// ---------------------------------------------------------------------------
// RMSNorm + Rotary + layout transform.  One warp per (b,n,h).
// qkv: [B,N,3,H,hd]  ->  Q/K/V: [B,H,N,hd]
// ---------------------------------------------------------------------------
__global__ __launch_bounds__(256) void norm_rope(
    const float* __restrict__ qkv,
    const float* __restrict__ qw, const float* __restrict__ kw,
    const float* __restrict__ cosb, const float* __restrict__ sinb,
    float* __restrict__ Q, float* __restrict__ K, float* __restrict__ V)
{
    int warp = (blockIdx.x * blockDim.x + threadIdx.x) >> 5;
    int lane = threadIdx.x & 31;
    if (warp >= B_ * N_ * H_) return;
    int h = warp % H_;
    int n = (warp / H_) % N_;
    int b = warp / (H_ * N_);

    const float* base = qkv + (size_t)(b * N_ + n) * 3 * C_ + h * HD_;
    int d0 = lane * 2;
    float q0 = base[d0],          q1 = base[d0 + 1];
    float k0 = base[C_ + d0],     k1 = base[C_ + d0 + 1];
    float v0 = base[2 * C_ + d0], v1 = base[2 * C_ + d0 + 1];

    float qs = q0 * q0 + q1 * q1;
    float ks = k0 * k0 + k1 * k1;
#pragma unroll
    for (int off = 16; off; off >>= 1) {
        qs += __shfl_xor_sync(0xffffffffu, qs, off);
        ks += __shfl_xor_sync(0xffffffffu, ks, off);
    }
    float qr = rsqrtf(qs * (1.f / HD_) + 1e-6f);
    float kr = rsqrtf(ks * (1.f / HD_) + 1e-6f);
    q0 = qw[d0] * q0 * qr; q1 = qw[d0 + 1] * q1 * qr;
    k0 = kw[d0] * k0 * kr; k1 = kw[d0 + 1] * k1 * kr;

    float c = cosb[n * 32 + lane];
    float s = sinb[n * 32 + lane];
    float qo0 = q0 * c - q1 * s, qo1 = q0 * s + q1 * c;
    float ko0 = k0 * c - k1 * s, ko1 = k0 * s + k1 * c;

    size_t oi = (((size_t)(b * H_ + h)) * N_ + n) * HD_ + d0;
    Q[oi] = qo0; Q[oi + 1] = qo1;
    K[oi] = ko0; K[oi + 1] = ko1;
    V[oi] = v0;  V[oi + 1] = v1;
}

// ---------------------------------------------------------------------------
// Causal flash attention. Block = 64 q-rows of one (b,h); 32-key tiles.
// Q/K/V: [B,H,N,hd].  Output written in [B,N,H*hd] layout.
// ---------------------------------------------------------------------------
__global__ __launch_bounds__(256) void attn_kernel(
    const float* __restrict__ Q, const float* __restrict__ K,
    const float* __restrict__ V, float* __restrict__ O)
{
    const int qt = blockIdx.x;   // q tile (64 rows)
    const int h  = blockIdx.y;
    const int b  = blockIdx.z;

    __shared__ alignas(16) float sQt[64][68];   // [d][r]
    __shared__ float sKt[64][33];               // [d][j]
    __shared__ alignas(16) float sV[32][68];    // [j][d]
    __shared__ float sS[64][33];                // [r][j]
    __shared__ float sM[64], sL[64], sAl[64];

    const int t    = threadIdx.x;
    const int tx   = t & 15;
    const int ty   = t >> 4;
    const int warp = t >> 5;
    const int lane = t & 31;

    size_t qbase = (((size_t)(b * H_ + h)) * N_ + qt * 64) * HD_;
#pragma unroll
    for (int i = 0; i < 16; i++) {
        int idx = t + i * 256;
        int r = idx >> 6, d = idx & 63;
        sQt[d][r] = Q[qbase + idx];
    }
    if (t < 64) { sM[t] = -INFINITY; sL[t] = 0.f; }

    float o[4][4];
#pragma unroll
    for (int i = 0; i < 4; i++)
#pragma unroll
        for (int j = 0; j < 4; j++) o[i][j] = 0.f;

    const int nkt = 2 * qt + 2;
    for (int kb = 0; kb < nkt; kb++) {
        __syncthreads();
        size_t kbase = (((size_t)(b * H_ + h)) * N_ + kb * 32) * HD_;
#pragma unroll
        for (int i = 0; i < 8; i++) {
            int idx = t + i * 256;
            int j = idx >> 6, d = idx & 63;
            sKt[d][j] = K[kbase + idx];
            sV[j][d]  = V[kbase + idx];
        }
        __syncthreads();

        // S = Q @ K^T on this tile
        float s[4][2] = {{0.f, 0.f}, {0.f, 0.f}, {0.f, 0.f}, {0.f, 0.f}};
#pragma unroll
        for (int d = 0; d < 64; d++) {
            float4 a = *(const float4*)&sQt[d][ty * 4];
            float b0 = sKt[d][tx * 2];
            float b1 = sKt[d][tx * 2 + 1];
            s[0][0] += a.x * b0; s[0][1] += a.x * b1;
            s[1][0] += a.y * b0; s[1][1] += a.y * b1;
            s[2][0] += a.z * b0; s[2][1] += a.z * b1;
            s[3][0] += a.w * b0; s[3][1] += a.w * b1;
        }
        const float scale = 0.125f;   // hd^-0.5
        const bool diag = (kb >= 2 * qt);
#pragma unroll
        for (int rr = 0; rr < 4; rr++)
#pragma unroll
            for (int cc = 0; cc < 2; cc++) {
                float val = s[rr][cc] * scale;
                if (diag && (kb * 32 + tx * 2 + cc) > (qt * 64 + ty * 4 + rr))
                    val = -1e30f;
                sS[ty * 4 + rr][tx * 2 + cc] = val;
            }
        __syncthreads();

        // online softmax: warp w -> rows 8w..8w+7, lane = key column
#pragma unroll
        for (int rr = 0; rr < 8; rr++) {
            int r = warp * 8 + rr;
            float v = sS[r][lane];
            float m = v;
#pragma unroll
            for (int off = 16; off; off >>= 1)
                m = fmaxf(m, __shfl_xor_sync(0xffffffffu, m, off));
            float mo = sM[r];
            float mn = fmaxf(mo, m);
            float p = __expf(v - mn);
            float sum = p;
#pragma unroll
            for (int off = 16; off; off >>= 1)
                sum += __shfl_xor_sync(0xffffffffu, sum, off);
            sS[r][lane] = p;
            if (lane == 0) {
                float al = __expf(mo - mn);
                sAl[r] = al;
                sM[r]  = mn;
                sL[r]  = sL[r] * al + sum;
            }
        }
        __syncthreads();

        // O = O*alpha + P @ V
#pragma unroll
        for (int rr = 0; rr < 4; rr++) {
            float al = sAl[ty * 4 + rr];
            o[rr][0] *= al; o[rr][1] *= al; o[rr][2] *= al; o[rr][3] *= al;
        }
#pragma unroll
        for (int j = 0; j < 32; j++) {
            float4 v4 = *(const float4*)&sV[j][tx * 4];
#pragma unroll
            for (int rr = 0; rr < 4; rr++) {
                float p = sS[ty * 4 + rr][j];
                o[rr][0] += p * v4.x; o[rr][1] += p * v4.y;
                o[rr][2] += p * v4.z; o[rr][3] += p * v4.w;
            }
        }
    }
    __syncthreads();

#pragma unroll
    for (int rr = 0; rr < 4; rr++) {
        int r = ty * 4 + rr;
        float inv = 1.f / sL[r];
        int qg = qt * 64 + r;
        size_t oi = ((size_t)(b * N_) + qg) * C_ + h * HD_ + tx * 4;
        O[oi + 0] = o[rr][0] * inv;
        O[oi + 1] = o[rr][1] * inv;
        O[oi + 2] = o[rr][2] * inv;
        O[oi + 3] = o[rr][3] * inv;
    }
}

// ---------------------------------------------------------------------------
extern "C" void kernel_launch(void* const* d_in, const int* in_sizes, int n_in,
                              void* d_out, int out_size)
{
    const float* x      = (const float*)d_in[0];
    const float* qkv_w  = (const float*)d_in[1];
    const float* qnw    = (const float*)d_in[2];
    const float* knw    = (const float*)d_in[3];
    const float* proj_w = (const float*)d_in[4];
    const float* proj_b = (const float*)d_in[5];
    const float* pcos   = (const float*)d_in[6];
    const float* psin   = (const float*)d_in[7];
    // d_in[8] = mask (tril) — causal, handled analytically
    float* out = (float*)d_out;

    void *p_qkv, *p_q, *p_k, *p_v, *p_att;
    cudaGetSymbolAddress(&p_qkv, g_qkv);
    cudaGetSymbolAddress(&p_q,   g_q);
    cudaGetSymbolAddress(&p_k,   g_k);
    cudaGetSymbolAddress(&p_v,   g_v);
    cudaGetSymbolAddress(&p_att, g_att);
    float* qkv = (float*)p_qkv;
    float* Qb  = (float*)p_q;
    float* Kb  = (float*)p_k;
    float* Vb  = (float*)p_v;
    float* att = (float*)p_att;

    const int M = B_ * N_;   // 4096

    // 1) QKV projection: [4096,1024] @ [3072,1024]^T -> [4096,3072]
    gemm_tf32<<<dim3(3 * C_ / 128, M / 128), 256>>>(x, qkv_w, nullptr, qkv,
                                                    M, 3 * C_, C_);
    // 2) RMSNorm + RoPE + transpose
    norm_rope<<<(B_ * N_ * H_ * 32) / 256, 256>>>(qkv, qnw, knw, pcos, psin,
                                                  Qb, Kb, Vb);
    // 3) Causal flash attention
    attn_kernel<<<dim3(N_ / 64, H_, B_), 256>>>(Qb, Kb, Vb, att);
    // 4) Output projection + bias
    gemm_tf32<<<dim3(C_ / 128, M / 128), 256>>>(att, proj_w, proj_b, out,
                                                M, C_, C_);
}

// round 3
// speedup vs baseline: 2.7392x; 1.9413x over previous
#include <cuda_runtime.h>
#include <cuda_bf16.h>
#include <math.h>

// Problem constants
#define B_  2
#define N_  2048
#define C_  1024
#define H_  16
#define HD_ 64

// Scratch (no allocation allowed -> device globals)
__device__ float g_qkv[B_ * N_ * 3 * C_];          // [B,N,3,H,hd]
__device__ float g_q[B_ * H_ * N_ * HD_];          // [B,H,N,hd]
__device__ float g_k[B_ * H_ * N_ * HD_];
__device__ float g_v[B_ * H_ * N_ * HD_];
__device__ float g_att[B_ * N_ * C_];              // [B,N,C]

// ---------------------------------------------------------------------------
// TF32 helpers
// ---------------------------------------------------------------------------
__device__ __forceinline__ float f2tf32(float x) {
    unsigned r;
    asm("cvt.rna.tf32.f32 %0, %1;" : "=r"(r) : "f"(x));
    return __uint_as_float(r);
}

__device__ __forceinline__ void mma1688(
    float& c0, float& c1, float& c2, float& c3,
    unsigned a0, unsigned a1, unsigned a2, unsigned a3,
    unsigned b0, unsigned b1)
{
    asm volatile(
        "mma.sync.aligned.m16n8k8.row.col.f32.tf32.tf32.f32 "
        "{%0,%1,%2,%3},{%4,%5,%6,%7},{%8,%9},{%0,%1,%2,%3};"
        : "+f"(c0), "+f"(c1), "+f"(c2), "+f"(c3)
        : "r"(a0), "r"(a1), "r"(a2), "r"(a3), "r"(b0), "r"(b1));
}

// ---------------------------------------------------------------------------
// TF32 tensor-core GEMM-NT: C[m][n] = sum_k A[m][k]*W[n][k] (+bias[n])
// ---------------------------------------------------------------------------
#define GPAD 20
__global__ __launch_bounds__(256) void gemm_tf32(
    const float* __restrict__ A, const float* __restrict__ W,
    const float* __restrict__ bias, float* __restrict__ Cout,
    int M, int N, int K)
{
    __shared__ alignas(16) float As[2][128 * GPAD];
    __shared__ alignas(16) float Bs[2][128 * GPAD];

    const int t    = threadIdx.x;
    const int bm   = blockIdx.y * 128;
    const int bn   = blockIdx.x * 128;
    const int warp = t >> 5;
    const int lane = t & 31;
    const int wm   = (warp >> 2) * 64;
    const int wn   = (warp & 3) * 32;
    const int g    = lane >> 2;
    const int tg   = lane & 3;

    float c[4][4][4];
#pragma unroll
    for (int i = 0; i < 4; i++)
#pragma unroll
        for (int j = 0; j < 4; j++)
#pragma unroll
            for (int q = 0; q < 4; q++) c[i][j][q] = 0.f;

    const int lr  = t >> 2;
    const int lkc = (t & 3) * 4;

    float4 pa0, pa1, pb0, pb1;

    pa0 = *(const float4*)&A[(size_t)(bm + lr)      * K + lkc];
    pa1 = *(const float4*)&A[(size_t)(bm + lr + 64) * K + lkc];
    pb0 = *(const float4*)&W[(size_t)(bn + lr)      * K + lkc];
    pb1 = *(const float4*)&W[(size_t)(bn + lr + 64) * K + lkc];
    {
        float4 ca0 = {f2tf32(pa0.x), f2tf32(pa0.y), f2tf32(pa0.z), f2tf32(pa0.w)};
        float4 ca1 = {f2tf32(pa1.x), f2tf32(pa1.y), f2tf32(pa1.z), f2tf32(pa1.w)};
        float4 cb0 = {f2tf32(pb0.x), f2tf32(pb0.y), f2tf32(pb0.z), f2tf32(pb0.w)};
        float4 cb1 = {f2tf32(pb1.x), f2tf32(pb1.y), f2tf32(pb1.z), f2tf32(pb1.w)};
        *(float4*)&As[0][lr * GPAD + lkc]        = ca0;
        *(float4*)&As[0][(lr + 64) * GPAD + lkc] = ca1;
        *(float4*)&Bs[0][lr * GPAD + lkc]        = cb0;
        *(float4*)&Bs[0][(lr + 64) * GPAD + lkc] = cb1;
    }
    __syncthreads();

    int buf = 0;
    for (int kt = 0; kt < K; kt += 16) {
        const bool more = (kt + 16) < K;
        if (more) {
            pa0 = *(const float4*)&A[(size_t)(bm + lr)      * K + kt + 16 + lkc];
            pa1 = *(const float4*)&A[(size_t)(bm + lr + 64) * K + kt + 16 + lkc];
            pb0 = *(const float4*)&W[(size_t)(bn + lr)      * K + kt + 16 + lkc];
            pb1 = *(const float4*)&W[(size_t)(bn + lr + 64) * K + kt + 16 + lkc];
        }

        const float* __restrict__ as = As[buf];
        const float* __restrict__ bs = Bs[buf];
#pragma unroll
        for (int ka = 0; ka < 2; ka++) {
            const int kb = ka * 8;
            unsigned af[4][4], bf[4][2];
#pragma unroll
            for (int am = 0; am < 4; am++) {
                const int m0 = wm + am * 16;
                af[am][0] = __float_as_uint(as[(m0 + g)     * GPAD + kb + tg]);
                af[am][1] = __float_as_uint(as[(m0 + 8 + g) * GPAD + kb + tg]);
                af[am][2] = __float_as_uint(as[(m0 + g)     * GPAD + kb + tg + 4]);
                af[am][3] = __float_as_uint(as[(m0 + 8 + g) * GPAD + kb + tg + 4]);
            }
#pragma unroll
            for (int an = 0; an < 4; an++) {
                const int n0 = wn + an * 8;
                bf[an][0] = __float_as_uint(bs[(n0 + g) * GPAD + kb + tg]);
                bf[an][1] = __float_as_uint(bs[(n0 + g) * GPAD + kb + tg + 4]);
            }
#pragma unroll
            for (int am = 0; am < 4; am++)
#pragma unroll
                for (int an = 0; an < 4; an++)
                    mma1688(c[am][an][0], c[am][an][1], c[am][an][2], c[am][an][3],
                            af[am][0], af[am][1], af[am][2], af[am][3],
                            bf[an][0], bf[an][1]);
        }

        if (more) {
            const int nb = buf ^ 1;
            float4 ca0 = {f2tf32(pa0.x), f2tf32(pa0.y), f2tf32(pa0.z), f2tf32(pa0.w)};
            float4 ca1 = {f2tf32(pa1.x), f2tf32(pa1.y), f2tf32(pa1.z), f2tf32(pa1.w)};
            float4 cb0 = {f2tf32(pb0.x), f2tf32(pb0.y), f2tf32(pb0.z), f2tf32(pb0.w)};
            float4 cb1 = {f2tf32(pb1.x), f2tf32(pb1.y), f2tf32(pb1.z), f2tf32(pb1.w)};
            *(float4*)&As[nb][lr * GPAD + lkc]        = ca0;
            *(float4*)&As[nb][(lr + 64) * GPAD + lkc] = ca1;
            *(float4*)&Bs[nb][lr * GPAD + lkc]        = cb0;
            *(float4*)&Bs[nb][(lr + 64) * GPAD + lkc] = cb1;
            __syncthreads();
            buf = nb;
        }
    }

#pragma unroll
    for (int am = 0; am < 4; am++) {
        const int r0 = bm + wm + am * 16 + g;
#pragma unroll
        for (int an = 0; an < 4; an++) {
            const int cc = bn + wn + an * 8 + 2 * tg;
            float b0 = 0.f, b1 = 0.f;
            if (bias) { b0 = bias[cc]; b1 = bias[cc + 1]; }
            float2 v0 = {c[am][an][0] + b0, c[am][an][1] + b1};
            float2 v1 = {c[am][an][2] + b0, c[am][an][3] + b1};
            *(float2*)&Cout[(size_t)r0 * N + cc]       = v0;
            *(float2*)&Cout[(size_t)(r0 + 8) * N + cc] = v1;
        }
    }
}

// ---------------------------------------------------------------------------
// RMSNorm + Rotary + layout transform.  One warp per (b,n,h).
// ---------------------------------------------------------------------------
__global__ __launch_bounds__(256) void norm_rope(
    const float* __restrict__ qkv,
    const float* __restrict__ qw, const float* __restrict__ kw,
    const float* __restrict__ cosb, const float* __restrict__ sinb,
    float* __restrict__ Q, float* __restrict__ K, float* __restrict__ V)
{
    int warp = (blockIdx.x * blockDim.x + threadIdx.x) >> 5;
    int lane = threadIdx.x & 31;
    if (warp >= B_ * N_ * H_) return;
    int h = warp % H_;
    int n = (warp / H_) % N_;
    int b = warp / (H_ * N_);

    const float* base = qkv + (size_t)(b * N_ + n) * 3 * C_ + h * HD_;
    int d0 = lane * 2;
    float q0 = base[d0],          q1 = base[d0 + 1];
    float k0 = base[C_ + d0],     k1 = base[C_ + d0 + 1];
    float v0 = base[2 * C_ + d0], v1 = base[2 * C_ + d0 + 1];

    float qs = q0 * q0 + q1 * q1;
    float ks = k0 * k0 + k1 * k1;
#pragma unroll
    for (int off = 16; off; off >>= 1) {
        qs += __shfl_xor_sync(0xffffffffu, qs, off);
        ks += __shfl_xor_sync(0xffffffffu, ks, off);
    }
    float qr = rsqrtf(qs * (1.f / HD_) + 1e-6f);
    float kr = rsqrtf(ks * (1.f / HD_) + 1e-6f);
    q0 = qw[d0] * q0 * qr; q1 = qw[d0 + 1] * q1 * qr;
    k0 = kw[d0] * k0 * kr; k1 = kw[d0 + 1] * k1 * kr;

    float c = cosb[n * 32 + lane];
    float s = sinb[n * 32 + lane];
    float qo0 = q0 * c - q1 * s, qo1 = q0 * s + q1 * c;
    float ko0 = k0 * c - k1 * s, ko1 = k0 * s + k1 * c;

    size_t oi = (((size_t)(b * H_ + h)) * N_ + n) * HD_ + d0;
    Q[oi] = qo0; Q[oi + 1] = qo1;
    K[oi] = ko0; K[oi + 1] = ko1;
    V[oi] = v0;  V[oi + 1] = v1;
}

// ---------------------------------------------------------------------------
// TF32 tensor-core causal flash attention.
// Block: 128 q-rows of one (b,h); 8 warps, each owns a 16-row strip.
// Key tiles of 64.  S = Q@K^T via mma (K split hi/lo for accuracy),
// softmax in registers, O += P@V via mma (P through smem).
// Q/K/V: [B,H,N,64].  Output in [B,N,H*64] layout.
// ---------------------------------------------------------------------------
#define SKH_OFF 0
#define SKL_OFF (64 * 68)
#define SV_OFF  (2 * 64 * 68)
#define SP_OFF  (2 * 64 * 68 + 64 * 72)
#define ATTN_SMEM_FLOATS (2 * 64 * 68 + 64 * 72 + 128 * 68)
#define ATTN_SMEM_BYTES  (ATTN_SMEM_FLOATS * 4)

__global__ __launch_bounds__(256) void attn_tc(
    const float* __restrict__ Q, const float* __restrict__ K,
    const float* __restrict__ V, float* __restrict__ O)
{
    extern __shared__ float sm[];
    float* sKh = sm + SKH_OFF;   // [64][68]
    float* sKl = sm + SKL_OFF;   // [64][68]
    float* sV  = sm + SV_OFF;    // [64][72]  (keys x d)
    float* sP  = sm + SP_OFF;    // [128][68] (also Q staging)

    const int qt = (gridDim.x - 1) - blockIdx.x;   // heavy blocks first
    const int h  = blockIdx.y;
    const int b  = blockIdx.z;

    const int t    = threadIdx.x;
    const int warp = t >> 5;
    const int lane = t & 31;
    const int g    = lane >> 2;
    const int tg   = lane & 3;

    const size_t bh = (size_t)(b * H_ + h) * N_;

    // ---- stage Q tile [128][64] into sP, then pull fragments -------------
    {
        const float* qg = Q + (bh + qt * 128) * HD_;
#pragma unroll
        for (int i = 0; i < 8; i++) {
            int lin = t * 4 + i * 1024;          // float4 granule
            int r = lin >> 6, cc = lin & 63;
            float4 v4 = *(const float4*)&qg[lin];
            *(float4*)&sP[r * 68 + cc] = v4;
        }
    }
    __syncthreads();

    unsigned qf[8][4];
    {
        const int r0 = warp * 16 + g;
#pragma unroll
        for (int a = 0; a < 8; a++) {
            qf[a][0] = __float_as_uint(f2tf32(sP[r0 * 68 + 8 * a + tg]));
            qf[a][1] = __float_as_uint(f2tf32(sP[(r0 + 8) * 68 + 8 * a + tg]));
            qf[a][2] = __float_as_uint(f2tf32(sP[r0 * 68 + 8 * a + tg + 4]));
            qf[a][3] = __float_as_uint(f2tf32(sP[(r0 + 8) * 68 + 8 * a + tg + 4]));
        }
    }

    float oc[8][4];
#pragma unroll
    for (int j = 0; j < 8; j++)
#pragma unroll
        for (int q = 0; q < 4; q++) oc[j][q] = 0.f;
    float m0 = -INFINITY, m1 = -INFINITY, l0 = 0.f, l1 = 0.f;

    const int row0 = qt * 128 + warp * 16 + g;
    const int row1 = row0 + 8;
    const int nkt  = 2 * qt + 2;

    for (int kb = 0; kb < nkt; kb++) {
        __syncthreads();
        // ---- load K (hi/lo split) and V tiles ----------------------------
        {
            const float* kg = K + (bh + kb * 64) * HD_;
            const float* vg = V + (bh + kb * 64) * HD_;
#pragma unroll
            for (int i = 0; i < 4; i++) {
                int lin4 = t + i * 256;            // float4 index
                int r = lin4 >> 4, cc = (lin4 & 15) * 4;
                float4 kk = *(const float4*)&kg[r * 64 + cc];
                float4 kh = {f2tf32(kk.x), f2tf32(kk.y), f2tf32(kk.z), f2tf32(kk.w)};
                float4 kl = {f2tf32(kk.x - kh.x), f2tf32(kk.y - kh.y),
                             f2tf32(kk.z - kh.z), f2tf32(kk.w - kh.w)};
                *(float4*)&sKh[r * 68 + cc] = kh;
                *(float4*)&sKl[r * 68 + cc] = kl;
                float4 vv = *(const float4*)&vg[r * 64 + cc];
                float4 vt = {f2tf32(vv.x), f2tf32(vv.y), f2tf32(vv.z), f2tf32(vv.w)};
                *(float4*)&sV[r * 72 + cc] = vt;
            }
        }
        __syncthreads();

        // ---- S = Q @ K^T  (hi + lo planes) -------------------------------
        float sc[8][4];
#pragma unroll
        for (int j = 0; j < 8; j++)
#pragma unroll
            for (int q = 0; q < 4; q++) sc[j][q] = 0.f;

#pragma unroll
        for (int a = 0; a < 8; a++) {
#pragma unroll
            for (int nn = 0; nn < 8; nn++) {
                const int kr = (8 * nn + g) * 68 + 8 * a + tg;
                unsigned bh0 = __float_as_uint(sKh[kr]);
                unsigned bh1 = __float_as_uint(sKh[kr + 4]);
                mma1688(sc[nn][0], sc[nn][1], sc[nn][2], sc[nn][3],
                        qf[a][0], qf[a][1], qf[a][2], qf[a][3], bh0, bh1);
                unsigned bl0 = __float_as_uint(sKl[kr]);
                unsigned bl1 = __float_as_uint(sKl[kr + 4]);
                mma1688(sc[nn][0], sc[nn][1], sc[nn][2], sc[nn][3],
                        qf[a][0], qf[a][1], qf[a][2], qf[a][3], bl0, bl1);
            }
        }

        // ---- scale + causal mask ----------------------------------------
        const int colb = kb * 64 + 2 * tg;
#pragma unroll
        for (int nn = 0; nn < 8; nn++) {
            int c0 = colb + nn * 8;
            sc[nn][0] = (c0     <= row0) ? sc[nn][0] * 0.125f : -1e30f;
            sc[nn][1] = (c0 + 1 <= row0) ? sc[nn][1] * 0.125f : -1e30f;
            sc[nn][2] = (c0     <= row1) ? sc[nn][2] * 0.125f : -1e30f;
            sc[nn][3] = (c0 + 1 <= row1) ? sc[nn][3] * 0.125f : -1e30f;
        }

        // ---- online softmax (register-resident, quad reductions) --------
        float mx0 = -INFINITY, mx1 = -INFINITY;
#pragma unroll
        for (int nn = 0; nn < 8; nn++) {
            mx0 = fmaxf(mx0, fmaxf(sc[nn][0], sc[nn][1]));
            mx1 = fmaxf(mx1, fmaxf(sc[nn][2], sc[nn][3]));
        }
        mx0 = fmaxf(mx0, __shfl_xor_sync(0xffffffffu, mx0, 1));
        mx0 = fmaxf(mx0, __shfl_xor_sync(0xffffffffu, mx0, 2));
        mx1 = fmaxf(mx1, __shfl_xor_sync(0xffffffffu, mx1, 1));
        mx1 = fmaxf(mx1, __shfl_xor_sync(0xffffffffu, mx1, 2));

        float mn0 = fmaxf(m0, mx0), mn1 = fmaxf(m1, mx1);
        float al0 = __expf(m0 - mn0), al1 = __expf(m1 - mn1);
        m0 = mn0; m1 = mn1;

        float rs0 = 0.f, rs1 = 0.f;
#pragma unroll
        for (int nn = 0; nn < 8; nn++) {
            float p0 = __expf(sc[nn][0] - mn0);
            float p1 = __expf(sc[nn][1] - mn0);
            float p2 = __expf(sc[nn][2] - mn1);
            float p3 = __expf(sc[nn][3] - mn1);
            rs0 += p0 + p1; rs1 += p2 + p3;
            sc[nn][0] = p0; sc[nn][1] = p1; sc[nn][2] = p2; sc[nn][3] = p3;
        }
        rs0 += __shfl_xor_sync(0xffffffffu, rs0, 1);
        rs0 += __shfl_xor_sync(0xffffffffu, rs0, 2);
        rs1 += __shfl_xor_sync(0xffffffffu, rs1, 1);
        rs1 += __shfl_xor_sync(0xffffffffu, rs1, 2);
        l0 = l0 * al0 + rs0;
        l1 = l1 * al1 + rs1;

        // rescale O
#pragma unroll
        for (int nn = 0; nn < 8; nn++) {
            oc[nn][0] *= al0; oc[nn][1] *= al0;
            oc[nn][2] *= al1; oc[nn][3] *= al1;
        }

        // ---- P -> smem (warp-local strip) -------------------------------
        {
            const int pr = warp * 16 + g;
#pragma unroll
            for (int nn = 0; nn < 8; nn++) {
                float2 lo = {f2tf32(sc[nn][0]), f2tf32(sc[nn][1])};
                float2 hi = {f2tf32(sc[nn][2]), f2tf32(sc[nn][3])};
                *(float2*)&sP[pr * 68 + nn * 8 + 2 * tg]       = lo;
                *(float2*)&sP[(pr + 8) * 68 + nn * 8 + 2 * tg] = hi;
            }
        }
        __syncwarp();

        // ---- O += P @ V --------------------------------------------------
        {
            const int pr = warp * 16 + g;
#pragma unroll
            for (int a = 0; a < 8; a++) {
                unsigned p0 = __float_as_uint(sP[pr * 68 + 8 * a + tg]);
                unsigned p1 = __float_as_uint(sP[(pr + 8) * 68 + 8 * a + tg]);
                unsigned p2 = __float_as_uint(sP[pr * 68 + 8 * a + tg + 4]);
                unsigned p3 = __float_as_uint(sP[(pr + 8) * 68 + 8 * a + tg + 4]);
#pragma unroll
                for (int nn = 0; nn < 8; nn++) {
                    unsigned b0 = __float_as_uint(sV[(8 * a + tg) * 72 + 8 * nn + g]);
                    unsigned b1 = __float_as_uint(sV[(8 * a + tg + 4) * 72 + 8 * nn + g]);
                    mma1688(oc[nn][0], oc[nn][1], oc[nn][2], oc[nn][3],
                            p0, p1, p2, p3, b0, b1);
                }
            }
        }
        __syncwarp();
    }

    // ---- epilogue: normalize + write [B,N,C] ---------------------------
    float inv0 = 1.f / l0, inv1 = 1.f / l1;
    size_t ob0 = ((size_t)(b * N_) + row0) * C_ + h * HD_;
    size_t ob1 = ((size_t)(b * N_) + row1) * C_ + h * HD_;
#pragma unroll
    for (int nn = 0; nn < 8; nn++) {
        float2 v0 = {oc[nn][0] * inv0, oc[nn][1] * inv0};
        float2 v1 = {oc[nn][2] * inv1, oc[nn][3] * inv1};
        *(float2*)&O[ob0 + nn * 8 + 2 * tg] = v0;
        *(float2*)&O[ob1 + nn * 8 + 2 * tg] = v1;
    }
}

// ---------------------------------------------------------------------------
extern "C" void kernel_launch(void* const* d_in, const int* in_sizes, int n_in,
                              void* d_out, int out_size)
{
    const float* x      = (const float*)d_in[0];
    const float* qkv_w  = (const float*)d_in[1];
    const float* qnw    = (const float*)d_in[2];
    const float* knw    = (const float*)d_in[3];
    const float* proj_w = (const float*)d_in[4];
    const float* proj_b = (const float*)d_in[5];
    const float* pcos   = (const float*)d_in[6];
    const float* psin   = (const float*)d_in[7];
    float* out = (float*)d_out;

    void *p_qkv, *p_q, *p_k, *p_v, *p_att;
    cudaGetSymbolAddress(&p_qkv, g_qkv);
    cudaGetSymbolAddress(&p_q,   g_q);
    cudaGetSymbolAddress(&p_k,   g_k);
    cudaGetSymbolAddress(&p_v,   g_v);
    cudaGetSymbolAddress(&p_att, g_att);
    float* qkv = (float*)p_qkv;
    float* Qb  = (float*)p_q;
    float* Kb  = (float*)p_k;
    float* Vb  = (float*)p_v;
    float* att = (float*)p_att;

    cudaFuncSetAttribute(attn_tc, cudaFuncAttributeMaxDynamicSharedMemorySize,
                         ATTN_SMEM_BYTES);

    const int M = B_ * N_;   // 4096

    // 1) QKV projection
    gemm_tf32<<<dim3(3 * C_ / 128, M / 128), 256>>>(x, qkv_w, nullptr, qkv,
                                                    M, 3 * C_, C_);
    // 2) RMSNorm + RoPE + transpose
    norm_rope<<<(B_ * N_ * H_ * 32) / 256, 256>>>(qkv, qnw, knw, pcos, psin,
                                                  Qb, Kb, Vb);
    // 3) Tensor-core causal flash attention
    attn_tc<<<dim3(N_ / 128, H_, B_), 256, ATTN_SMEM_BYTES>>>(Qb, Kb, Vb, att);
    // 4) Output projection + bias
    gemm_tf32<<<dim3(C_ / 128, M / 128), 256>>>(att, proj_w, proj_b, out,
                                                M, C_, C_);
}